// round 3
// baseline (speedup 1.0000x reference)
#include <cuda_runtime.h>

#define NQ  6
#define NL  3
#define TPB 256
// 4 rows per thread = 24 floats = 6 float4 in / 6 float4 out.

__device__ __forceinline__ float sqrt_approx(float x) {
    float r; asm("sqrt.approx.f32 %0, %1;" : "=f"(r) : "f"(x)); return r;
}

__global__ void __launch_bounds__(TPB)
qc_fused(const float4* __restrict__ x4, float4* __restrict__ o4,
         const float* __restrict__ rp, const float* __restrict__ ep,
         int n_threads) {
    // ---- per-block derived constants in shared memory ----
    __shared__ float sC [NL * NQ];        // cos(rx/2)
    __shared__ float sS [NL * NQ];        // sin(rx/2)
    __shared__ float sT [NL * (NQ - 1)];  // sigmoid(ep)*0.5
    __shared__ float sOT[NL * (NQ - 1)];  // 1 - sigmoid(ep)*0.5

    int tid = threadIdx.x;
    if (tid < NL * NQ) {
        float rx = rp[tid * 3];           // rotation_params[l][q][0], tid = l*NQ+q
        float s, c;
        sincosf(rx * 0.5f, &s, &c);
        sC[tid] = c;
        sS[tid] = s;
    } else if (tid < NL * NQ + NL * (NQ - 1)) {
        int k = tid - NL * NQ;
        float e  = ep[k];
        float t  = 0.5f / (1.0f + expf(-e));   // sigmoid * 0.5
        sT[k]  = t;
        sOT[k] = 1.0f - t;
    }
    __syncthreads();

    int t0 = blockIdx.x * TPB + tid;
    if (t0 >= n_threads) return;
    long base = (long)t0 * 6;             // 6 float4 per thread

    // front-batched streaming loads (L2 evict-first)
    float4 v[6];
#pragma unroll
    for (int i = 0; i < 6; i++) v[i] = __ldcs(&x4[base + i]);

    const float* in = reinterpret_cast<const float*>(v);
    float outv[24];
    const float PIH = 1.57079632679489662f;

#pragma unroll
    for (int r = 0; r < 4; r++) {
        float sr[NQ], si[NQ];
#pragma unroll
        for (int q = 0; q < NQ; q++) {
            __sincosf(in[r * NQ + q] * PIH, &si[q], &sr[q]);  // real=cos, imag=sin
        }

#pragma unroll
        for (int l = 0; l < NL; l++) {
            // rotation: nr = c*sr + s*si ; ni = c*si - s*sr
#pragma unroll
            for (int q = 0; q < NQ; q++) {
                float c = sC[l * NQ + q];
                float s = sS[l * NQ + q];
                float nr = fmaf(c, sr[q],  s * si[q]);
                float ni = fmaf(c, si[q], -s * sr[q]);
                sr[q] = nr; si[q] = ni;
            }
            // mixing: new[q] = (1-t)*sr[q] + t*sr_old[q+1]   (t = sigmoid/2)
            float old4 = sr[4];
#pragma unroll
            for (int q = 0; q < NQ - 1; q++) {
                sr[q] = fmaf(sOT[l * 5 + q], sr[q], sT[l * 5 + q] * sr[q + 1]);
            }
            sr[5] = fmaf(sOT[l * 5 + 4], sr[5], sT[l * 5 + 4] * old4);
        }

        // magnitude: sqrt(sr^2 + si^2)  (MUFU.SQRT approx; inputs are O(1))
#pragma unroll
        for (int q = 0; q < NQ; q++) {
            outv[r * NQ + q] = sqrt_approx(fmaf(sr[q], sr[q], si[q] * si[q]));
        }
    }

    // streaming stores
#pragma unroll
    for (int i = 0; i < 6; i++) {
        float4 w = make_float4(outv[4*i], outv[4*i+1], outv[4*i+2], outv[4*i+3]);
        __stcs(&o4[base + i], w);
    }
}

extern "C" void kernel_launch(void* const* d_in, const int* in_sizes, int n_in,
                              void* d_out, int out_size) {
    const float* x  = (const float*)d_in[0];  // (BATCH, 6) fp32
    const float* rp = (const float*)d_in[1];  // (3, 6, 3) fp32
    const float* ep = (const float*)d_in[2];  // (3, 5)    fp32
    float* out = (float*)d_out;

    int total_f   = in_sizes[0];                  // BATCH * 6
    int n_threads = total_f / 24;                 // 4 rows per thread
    int blocks    = (n_threads + TPB - 1) / TPB;

    qc_fused<<<blocks, TPB>>>((const float4*)x, (float4*)out, rp, ep, n_threads);
}

// round 4
// speedup vs baseline: 1.3338x; 1.3338x over previous
#include <cuda_runtime.h>

#define NQ  6
#define NL  3
#define TPB 128
// 2 rows per thread = 12 floats = 3 float4 in / 3 float4 out.

__device__ __forceinline__ float sqrt_approx(float x) {
    float r; asm("sqrt.approx.f32 %0, %1;" : "=f"(r) : "f"(x)); return r;
}

__global__ void __launch_bounds__(TPB, 10)
qc_fused(const float4* __restrict__ x4, float4* __restrict__ o4,
         const float* __restrict__ rp, const float* __restrict__ ep,
         int n_threads) {
    // constants packed for LDS.64 broadcast:
    // sCS[l*6+q] = (cos(rx/2), sin(rx/2)); sTT[l*5+k] = (1-t, t), t=sigmoid/2
    __shared__ float2 sCS[NL * NQ];
    __shared__ float2 sTT[NL * (NQ - 1)];

    int tid = threadIdx.x;
    if (tid < NL * NQ) {
        float rx = __ldg(&rp[tid * 3]);
        float s, c;
        __sincosf(rx * 0.5f, &s, &c);     // approx: no slow-path reg bloat
        sCS[tid] = make_float2(c, s);
    } else if (tid < NL * NQ + NL * (NQ - 1)) {
        int k = tid - NL * NQ;
        float t = 0.5f / (1.0f + __expf(-__ldg(&ep[k])));
        sTT[k] = make_float2(1.0f - t, t);
    }
    __syncthreads();

    int t0 = blockIdx.x * TPB + tid;
    if (t0 >= n_threads) return;
    int base = t0 * 3;                    // 3 float4 per thread

    float4 v0 = __ldcs(x4 + base);
    float4 v1 = __ldcs(x4 + base + 1);
    float4 v2 = __ldcs(x4 + base + 2);

    const float PIH = 1.57079632679489662f;
    float sr[12], si[12];
    {
        float in[12] = {v0.x, v0.y, v0.z, v0.w,
                        v1.x, v1.y, v1.z, v1.w,
                        v2.x, v2.y, v2.z, v2.w};
#pragma unroll
        for (int i = 0; i < 12; i++)
            __sincosf(in[i] * PIH, &si[i], &sr[i]);   // real=cos, imag=sin
    }

    // layers outer, both rows inner: each constant LDS reused for 2 rows
#pragma unroll
    for (int l = 0; l < NL; l++) {
#pragma unroll
        for (int q = 0; q < NQ; q++) {
            float2 cs = sCS[l * NQ + q];
#pragma unroll
            for (int r = 0; r < 2; r++) {
                int i = r * 6 + q;
                float nr = fmaf(cs.x, sr[i],  cs.y * si[i]);
                float ni = fmaf(cs.x, si[i], -cs.y * sr[i]);
                sr[i] = nr; si[i] = ni;
            }
        }
        // mixing: new[k] = (1-t)*sr[k] + t*sr_old[k+1]
        float old4a = sr[4], old4b = sr[10];
#pragma unroll
        for (int k = 0; k < NQ - 1; k++) {
            float2 tt = sTT[l * 5 + k];
            sr[k]     = fmaf(tt.x, sr[k],     tt.y * sr[k + 1]);
            sr[6 + k] = fmaf(tt.x, sr[6 + k], tt.y * sr[7 + k]);
        }
        {
            float2 tt = sTT[l * 5 + 4];
            sr[5]  = fmaf(tt.x, sr[5],  tt.y * old4a);
            sr[11] = fmaf(tt.x, sr[11], tt.y * old4b);
        }
    }

    float o[12];
#pragma unroll
    for (int i = 0; i < 12; i++)
        o[i] = sqrt_approx(fmaf(sr[i], sr[i], si[i] * si[i]));

    __stcs(o4 + base,     make_float4(o[0], o[1], o[2],  o[3]));
    __stcs(o4 + base + 1, make_float4(o[4], o[5], o[6],  o[7]));
    __stcs(o4 + base + 2, make_float4(o[8], o[9], o[10], o[11]));
}

extern "C" void kernel_launch(void* const* d_in, const int* in_sizes, int n_in,
                              void* d_out, int out_size) {
    const float* x  = (const float*)d_in[0];  // (BATCH, 6) fp32
    const float* rp = (const float*)d_in[1];  // (3, 6, 3) fp32
    const float* ep = (const float*)d_in[2];  // (3, 5)    fp32
    float* out = (float*)d_out;

    int total_f   = in_sizes[0];                  // BATCH * 6
    int n_threads = total_f / 12;                 // 2 rows per thread
    int blocks    = (n_threads + TPB - 1) / TPB;

    qc_fused<<<blocks, TPB>>>((const float4*)x, (float4*)out, rp, ep, n_threads);
}

// round 5
// speedup vs baseline: 1.4893x; 1.1165x over previous
#include <cuda_runtime.h>

#define NQ  6
#define NL  3
#define TPB 128
// 2 rows per thread = 12 floats = 3 float4 in / 3 float4 out.

__device__ __forceinline__ float sqrt_approx(float x) {
    float r; asm("sqrt.approx.f32 %0, %1;" : "=f"(r) : "f"(x)); return r;
}

__global__ void __launch_bounds__(TPB, 12)
qc_fused(const float4* __restrict__ x4, float4* __restrict__ o4,
         const float* __restrict__ rp, const float* __restrict__ ep,
         int n_threads) {
    // sTh0[q]      = rx[0][q]*0.5            (layer-0 rotation folded into entry phase)
    // sCS[l-1][q]  = (cos(rx/2), sin(rx/2))  for layers 1,2
    // sTT[l][k]    = (1-t, t), t = sigmoid(ep)/2
    __shared__ float  sTh0[NQ];
    __shared__ float2 sCS[(NL - 1) * NQ];
    __shared__ float2 sTT[NL * (NQ - 1)];

    int tid = threadIdx.x;
    if (tid < NL * NQ) {
        float rx = __ldg(&rp[tid * 3]) * 0.5f;
        if (tid < NQ) {
            sTh0[tid] = rx;
        } else {
            float s, c;
            __sincosf(rx, &s, &c);
            sCS[tid - NQ] = make_float2(c, s);
        }
    } else if (tid < NL * NQ + NL * (NQ - 1)) {
        int k = tid - NL * NQ;
        float t = 0.5f / (1.0f + __expf(-__ldg(&ep[k])));
        sTT[k] = make_float2(1.0f - t, t);
    }
    __syncthreads();

    int t0 = blockIdx.x * TPB + tid;
    if (t0 >= n_threads) return;
    int base = t0 * 3;                    // 3 float4 per thread

    float4 v0 = __ldcs(x4 + base);
    float4 v1 = __ldcs(x4 + base + 1);
    float4 v2 = __ldcs(x4 + base + 2);

    const float PIH = 1.57079632679489662f;
    float sr[12], si[12];
    {
        float in[12] = {v0.x, v0.y, v0.z, v0.w,
                        v1.x, v1.y, v1.z, v1.w,
                        v2.x, v2.y, v2.z, v2.w};
        // entry + layer-0 rotation fused: state = e^{i(half - th0_q)}
#pragma unroll
        for (int i = 0; i < 12; i++) {
            float ang = fmaf(in[i], PIH, -sTh0[i % NQ]);
            __sincosf(ang, &si[i], &sr[i]);   // real=cos, imag=sin
        }
    }

#pragma unroll
    for (int l = 0; l < NL; l++) {
        if (l > 0) {
            // rotation for layers 1,2: nr = c*sr + s*si ; ni = c*si - s*sr
#pragma unroll
            for (int q = 0; q < NQ; q++) {
                float2 cs = sCS[(l - 1) * NQ + q];
#pragma unroll
                for (int r = 0; r < 2; r++) {
                    int i = r * 6 + q;
                    float nr = fmaf(cs.x, sr[i],  cs.y * si[i]);
                    float ni = fmaf(cs.x, si[i], -cs.y * sr[i]);
                    sr[i] = nr; si[i] = ni;
                }
            }
        }
        // mixing: new[k] = (1-t)*sr[k] + t*sr_old[k+1]
        float old4a = sr[4], old4b = sr[10];
#pragma unroll
        for (int k = 0; k < NQ - 1; k++) {
            float2 tt = sTT[l * 5 + k];
            sr[k]     = fmaf(tt.x, sr[k],     tt.y * sr[k + 1]);
            sr[6 + k] = fmaf(tt.x, sr[6 + k], tt.y * sr[7 + k]);
        }
        {
            float2 tt = sTT[l * 5 + 4];
            sr[5]  = fmaf(tt.x, sr[5],  tt.y * old4a);
            sr[11] = fmaf(tt.x, sr[11], tt.y * old4b);
        }
    }

    float o[12];
#pragma unroll
    for (int i = 0; i < 12; i++)
        o[i] = sqrt_approx(fmaf(sr[i], sr[i], si[i] * si[i]));

    __stcs(o4 + base,     make_float4(o[0], o[1], o[2],  o[3]));
    __stcs(o4 + base + 1, make_float4(o[4], o[5], o[6],  o[7]));
    __stcs(o4 + base + 2, make_float4(o[8], o[9], o[10], o[11]));
}

extern "C" void kernel_launch(void* const* d_in, const int* in_sizes, int n_in,
                              void* d_out, int out_size) {
    const float* x  = (const float*)d_in[0];  // (BATCH, 6) fp32
    const float* rp = (const float*)d_in[1];  // (3, 6, 3) fp32
    const float* ep = (const float*)d_in[2];  // (3, 5)    fp32
    float* out = (float*)d_out;

    int total_f   = in_sizes[0];                  // BATCH * 6
    int n_threads = total_f / 12;                 // 2 rows per thread
    int blocks    = (n_threads + TPB - 1) / TPB;

    qc_fused<<<blocks, TPB>>>((const float4*)x, (float4*)out, rp, ep, n_threads);
}